// round 15
// baseline (speedup 1.0000x reference)
#include <cuda_runtime.h>

// ConvKB: score[e] = sum_{c,d} relu(w0c*u_d + w1c*v_d + w2c*r_d + bc) * lw[c,d] + lb
// Warp = (2 edges, 4 channels, all 128 d); block = 16 channels; 2 blocks per edge
// pair (blockIdx&1 selects channel half). ~105 regs -> 4 blocks/SM = 16 warps/SM.
// Indices staged 1 iter ahead; 4 independent FFMA2 chains; 3-level butterfly +
// 4-lane atomicAdd. Packed f32x2 FMA, relu via (t+|t|) with lw pre-scaled 0.5.

#define D 128
#define THREADS 128
#define NBLK 592              // 148 SMs * 4 blocks
#define P 296                 // edge-pairs in flight (NBLK/2)
#define NEDGE 50000

typedef unsigned long long ull;

__device__ int g_is64;        // 1 if index arrays are int64, 0 if int32

__device__ __forceinline__ ull ffma2(ull a, ull b, ull c) {
    ull d;
    asm("fma.rn.f32x2 %0, %1, %2, %3;" : "=l"(d) : "l"(a), "l"(b), "l"(c));
    return d;
}
__device__ __forceinline__ ull fadd2(ull a, ull b) {
    ull d;
    asm("add.rn.f32x2 %0, %1, %2;" : "=l"(d) : "l"(a), "l"(b));
    return d;
}
// 2*relu(a) packed: a + |a|
__device__ __forceinline__ ull relu2x2(ull a) {
    return fadd2(a, a & 0x7FFFFFFF7FFFFFFFULL);
}
__device__ __forceinline__ ull pack2(float lo, float hi) {
    ull d;
    asm("mov.b64 %0, {%1, %2};" : "=l"(d) : "f"(lo), "f"(hi));
    return d;
}
__device__ __forceinline__ float2 unpack2(ull v) {
    float2 r;
    asm("mov.b64 {%0, %1}, %2;" : "=f"(r.x), "=f"(r.y) : "l"(v));
    return r;
}

// Fused: dtype detection (thread 0) + out[] init to lin_b.
__global__ void init_kernel(float* __restrict__ out, const float* __restrict__ lin_b,
                            const int* __restrict__ ei) {
    int i = blockIdx.x * blockDim.x + threadIdx.x;
    if (i == 0) {
        int is64 = 1;
        for (int k = 1; k < 128; k += 2)
            if (ei[k] != 0) { is64 = 0; break; }
        g_is64 = is64;
    }
    if (i < NEDGE) out[i] = lin_b[0];
}

__global__ void __launch_bounds__(THREADS, 4) convkb_kernel(
    const float* __restrict__ h,
    const float* __restrict__ g,
    const int* __restrict__ edge_idx,    // [2,E], low int32 words read
    const int* __restrict__ edge_type,   // [E]
    const float* __restrict__ conv_w,    // [C,3]
    const float* __restrict__ conv_b,    // [C]
    const float* __restrict__ lin_w,     // [C*D]
    float* __restrict__ out)             // [E], pre-initialized to lin_b
{
    const int lane = threadIdx.x & 31;
    const int warp = threadIdx.x >> 5;
    const int pairId = (int)blockIdx.x >> 1;       // 0..P-1

    // ---- Edge-invariant register state: warp covers 4 channels ----
    // Lane L owns d = 4L .. 4L+3 (two packed d-pairs). Shared by both edges.
    const int cb = ((int)blockIdx.x & 1) * 16 + warp * 4;
    ull w0d[4], w1d[4], w2d[4], bd[4], lwr[4][2];
    {
        const float4* lw4 = (const float4*)lin_w;
#pragma unroll
        for (int ch = 0; ch < 4; ++ch) {
            int c = cb + ch;
            float a0 = conv_w[3 * c + 0], a1 = conv_w[3 * c + 1], a2 = conv_w[3 * c + 2];
            float bb = conv_b[c];
            w0d[ch] = pack2(a0, a0);
            w1d[ch] = pack2(a1, a1);
            w2d[ch] = pack2(a2, a2);
            bd[ch]  = pack2(bb, bb);
            float4 A = lw4[c * 32 + lane];   // lw[c, 4L .. 4L+3]
            lwr[ch][0] = pack2(0.5f * A.x, 0.5f * A.y);   // relu-trick pre-scale
            lwr[ch][1] = pack2(0.5f * A.z, 0.5f * A.w);
        }
    }

    const int stride = g_is64 ? 2 : 1;

    // ---- Prologue: stage indices for pair(0) = (e0, e0+P) ----
    int e = pairId;
    int rowA = edge_idx[(size_t)stride * e];
    int colA = edge_idx[(size_t)stride * (NEDGE + e)];
    int relA = edge_type[(size_t)stride * e];
    int eb0 = e + P;                               // < 592 < NEDGE: safe
    int rowB = edge_idx[(size_t)stride * eb0];
    int colB = edge_idx[(size_t)stride * (NEDGE + eb0)];
    int relB = edge_type[(size_t)stride * eb0];

    for (; e < NEDGE; e += 2 * P) {
        // ---- Gathers for current pair (indices staged last iteration) ----
        ulonglong2 RA = ((const ulonglong2*)(g + (size_t)relA * D))[lane];
        ulonglong2 RB = ((const ulonglong2*)(g + (size_t)relB * D))[lane];
        ulonglong2 VA = ((const ulonglong2*)(h + (size_t)colA * D))[lane];
        ulonglong2 VB = ((const ulonglong2*)(h + (size_t)colB * D))[lane];
        ulonglong2 UA = ((const ulonglong2*)(h + (size_t)rowA * D))[lane];
        ulonglong2 UB = ((const ulonglong2*)(h + (size_t)rowB * D))[lane];

        // ---- Stage indices for next pair ----
        int ea2 = min(e + 2 * P, NEDGE - 1);       // clamp: safe addr, discarded
        int eb2 = min(e + 3 * P, NEDGE - 1);
        rowA = edge_idx[(size_t)stride * ea2];
        colA = edge_idx[(size_t)stride * (NEDGE + ea2)];
        relA = edge_type[(size_t)stride * ea2];
        rowB = edge_idx[(size_t)stride * eb2];
        colB = edge_idx[(size_t)stride * (NEDGE + eb2)];
        relB = edge_type[(size_t)stride * eb2];

        // ---- Compute both edges (4 independent FFMA2 chains; shared params) ----
        ull a0A = 0ULL, a1A = 0ULL, a0B = 0ULL, a1B = 0ULL;
#pragma unroll
        for (int ch = 0; ch < 4; ++ch) {
            ull t0a = ffma2(w2d[ch], RA.x, bd[ch]);
            ull t1a = ffma2(w2d[ch], RA.y, bd[ch]);
            ull t0b = ffma2(w2d[ch], RB.x, bd[ch]);
            ull t1b = ffma2(w2d[ch], RB.y, bd[ch]);
            t0a = ffma2(w1d[ch], VA.x, t0a);
            t1a = ffma2(w1d[ch], VA.y, t1a);
            t0b = ffma2(w1d[ch], VB.x, t0b);
            t1b = ffma2(w1d[ch], VB.y, t1b);
            t0a = ffma2(w0d[ch], UA.x, t0a);
            t1a = ffma2(w0d[ch], UA.y, t1a);
            t0b = ffma2(w0d[ch], UB.x, t0b);
            t1b = ffma2(w0d[ch], UB.y, t1b);
            t0a = relu2x2(t0a);
            t1a = relu2x2(t1a);
            t0b = relu2x2(t0b);
            t1b = relu2x2(t1b);
            a0A = ffma2(t0a, lwr[ch][0], a0A);
            a1A = ffma2(t1a, lwr[ch][1], a1A);
            a0B = ffma2(t0b, lwr[ch][0], a0B);
            a1B = ffma2(t1b, lwr[ch][1], a1B);
        }
        float2 fA = unpack2(fadd2(a0A, a1A));
        float2 fB = unpack2(fadd2(a0B, a1B));
        float sA = fA.x + fA.y;
        float sB = fB.x + fB.y;
        // 3-level butterfly: lanes 0..3 hold 4 disjoint partials.
#pragma unroll
        for (int off = 16; off >= 4; off >>= 1) {
            sA += __shfl_xor_sync(0xffffffffu, sA, off);
            sB += __shfl_xor_sync(0xffffffffu, sB, off);
        }
        if (lane < 4) {
            atomicAdd(out + e, sA);
            int eb = e + P;
            if (eb < NEDGE) atomicAdd(out + eb, sB);
        }
    }
}

extern "C" void kernel_launch(void* const* d_in, const int* in_sizes, int n_in,
                              void* d_out, int out_size) {
    // Identify inputs by unique element counts (immune to metadata ordering).
    const float *h = 0, *g = 0, *conv_w = 0, *conv_b = 0, *lin_w = 0, *lin_b = 0;
    const int *edge_idx = 0, *edge_type = 0;
    for (int i = 0; i < n_in; ++i) {
        switch (in_sizes[i]) {
            case NEDGE * 128: h         = (const float*)d_in[i]; break;
            case 500 * 128:   g         = (const float*)d_in[i]; break;
            case 2 * NEDGE:   edge_idx  = (const int*)d_in[i];   break;
            case NEDGE:       edge_type = (const int*)d_in[i];   break;
            case 96:          conv_w    = (const float*)d_in[i]; break;
            case 32:          conv_b    = (const float*)d_in[i]; break;
            case 4096:        lin_w     = (const float*)d_in[i]; break;
            case 1:           lin_b     = (const float*)d_in[i]; break;
            default: break;
        }
    }
    float* out = (float*)d_out;

    init_kernel<<<(NEDGE + 255) / 256, 256>>>(out, lin_b, edge_idx);
    convkb_kernel<<<NBLK, THREADS>>>(h, g, edge_idx, edge_type,
                                     conv_w, conv_b, lin_w, out);
}

// round 16
// speedup vs baseline: 1.1299x; 1.1299x over previous
#include <cuda_runtime.h>

// ConvKB: score[e] = sum_{c,d} relu(w0c*u_d + w1c*v_d + w2c*r_d + bc) * lw[c,d] + lb
// Warp = (2 ADJACENT edges, 8 channels, all 128 d). Adjacent pairing -> 3 vector
// index loads/iter (not 6), no tail checks (25000 exact pairs). Indices staged 1
// iter ahead (before gathers). 4 independent FFMA2 chains; 2-level butterfly +
// 8-lane atomicAdd. Packed f32x2 FMA, relu via (t+|t|), lw pre-scaled 0.5.

#define D 128
#define THREADS 128
#define G 444                 // grid: 148 SMs * 3 blocks
#define NPAIR 25000           // NEDGE/2 exact
#define NEDGE 50000

typedef unsigned long long ull;

__device__ int g_is64;        // 1 if index arrays are int64, 0 if int32

__device__ __forceinline__ ull ffma2(ull a, ull b, ull c) {
    ull d;
    asm("fma.rn.f32x2 %0, %1, %2, %3;" : "=l"(d) : "l"(a), "l"(b), "l"(c));
    return d;
}
__device__ __forceinline__ ull fadd2(ull a, ull b) {
    ull d;
    asm("add.rn.f32x2 %0, %1, %2;" : "=l"(d) : "l"(a), "l"(b));
    return d;
}
// 2*relu(a) packed: a + |a|
__device__ __forceinline__ ull relu2x2(ull a) {
    return fadd2(a, a & 0x7FFFFFFF7FFFFFFFULL);
}
__device__ __forceinline__ ull pack2(float lo, float hi) {
    ull d;
    asm("mov.b64 %0, {%1, %2};" : "=l"(d) : "f"(lo), "f"(hi));
    return d;
}
__device__ __forceinline__ float2 unpack2(ull v) {
    float2 r;
    asm("mov.b64 {%0, %1}, %2;" : "=f"(r.x), "=f"(r.y) : "l"(v));
    return r;
}

// Load the index pair (edge 2p, 2p+1) from base+off in one vector load.
__device__ __forceinline__ int2 idx_pair(const int* base, int off2, int is64) {
    if (is64) {
        longlong2 t = ((const longlong2*)base)[off2 >> 1];   // off2 = 2p (even)
        return make_int2((int)t.x, (int)t.y);
    } else {
        return ((const int2*)base)[off2 >> 1];
    }
}

// Fused: dtype detection (thread 0) + out[] init to lin_b.
__global__ void init_kernel(float* __restrict__ out, const float* __restrict__ lin_b,
                            const int* __restrict__ ei) {
    int i = blockIdx.x * blockDim.x + threadIdx.x;
    if (i == 0) {
        int is64 = 1;
        for (int k = 1; k < 128; k += 2)
            if (ei[k] != 0) { is64 = 0; break; }
        g_is64 = is64;
    }
    if (i < NEDGE) out[i] = lin_b[0];
}

__global__ void __launch_bounds__(THREADS, 3) convkb_kernel(
    const float* __restrict__ h,
    const float* __restrict__ g,
    const int* __restrict__ edge_idx,    // [2,E], int32 or int64
    const int* __restrict__ edge_type,   // [E]
    const float* __restrict__ conv_w,    // [C,3]
    const float* __restrict__ conv_b,    // [C]
    const float* __restrict__ lin_w,     // [C*D]
    float* __restrict__ out)             // [E], pre-initialized to lin_b
{
    const int lane = threadIdx.x & 31;
    const int warp = threadIdx.x >> 5;

    // ---- Edge-invariant register state: warp covers channels cb..cb+7 ----
    // Lane L owns d = 4L .. 4L+3 (two packed d-pairs). Shared by both edges.
    const int cb = warp * 8;
    ull w0d[8], w1d[8], w2d[8], bd[8], lwr[8][2];
    {
        const float4* lw4 = (const float4*)lin_w;
#pragma unroll
        for (int ch = 0; ch < 8; ++ch) {
            int c = cb + ch;
            float a0 = conv_w[3 * c + 0], a1 = conv_w[3 * c + 1], a2 = conv_w[3 * c + 2];
            float bb = conv_b[c];
            w0d[ch] = pack2(a0, a0);
            w1d[ch] = pack2(a1, a1);
            w2d[ch] = pack2(a2, a2);
            bd[ch]  = pack2(bb, bb);
            float4 A = lw4[c * 32 + lane];   // lw[c, 4L .. 4L+3]
            lwr[ch][0] = pack2(0.5f * A.x, 0.5f * A.y);   // relu-trick pre-scale
            lwr[ch][1] = pack2(0.5f * A.z, 0.5f * A.w);
        }
    }

    const int is64 = g_is64;
    // int64 arrays: byte offsets double; idx_pair handles layout via is64.
    const int* eidx_rows = edge_idx;                          // rows at [0..E)
    const int* eidx_cols = edge_idx + (is64 ? 2 * NEDGE : NEDGE);  // cols at [E..2E)

    // ---- Prologue: stage index pairs for pair(0) ----
    int p = (int)blockIdx.x;
    int2 rw = idx_pair(eidx_rows, 2 * p, is64);
    int2 cl = idx_pair(eidx_cols, 2 * p, is64);
    int2 tp = idx_pair(edge_type, 2 * p, is64);

    for (; p < NPAIR; p += G) {
        // ---- Stage index pairs for next iteration FIRST (longest chain) ----
        int pn = min(p + G, NPAIR - 1);            // clamp: safe, discarded at end
        int2 rw1 = idx_pair(eidx_rows, 2 * pn, is64);
        int2 cl1 = idx_pair(eidx_cols, 2 * pn, is64);
        int2 tp1 = idx_pair(edge_type, 2 * pn, is64);

        // ---- Gathers for current pair ----
        ulonglong2 RA = ((const ulonglong2*)(g + (size_t)tp.x * D))[lane];
        ulonglong2 RB = ((const ulonglong2*)(g + (size_t)tp.y * D))[lane];
        ulonglong2 VA = ((const ulonglong2*)(h + (size_t)cl.x * D))[lane];
        ulonglong2 VB = ((const ulonglong2*)(h + (size_t)cl.y * D))[lane];
        ulonglong2 UA = ((const ulonglong2*)(h + (size_t)rw.x * D))[lane];
        ulonglong2 UB = ((const ulonglong2*)(h + (size_t)rw.y * D))[lane];

        // ---- Compute both edges (4 independent FFMA2 chains; shared params) ----
        ull a0A = 0ULL, a1A = 0ULL, a0B = 0ULL, a1B = 0ULL;
#pragma unroll
        for (int ch = 0; ch < 8; ++ch) {
            ull t0a = ffma2(w2d[ch], RA.x, bd[ch]);
            ull t1a = ffma2(w2d[ch], RA.y, bd[ch]);
            ull t0b = ffma2(w2d[ch], RB.x, bd[ch]);
            ull t1b = ffma2(w2d[ch], RB.y, bd[ch]);
            t0a = ffma2(w1d[ch], VA.x, t0a);
            t1a = ffma2(w1d[ch], VA.y, t1a);
            t0b = ffma2(w1d[ch], VB.x, t0b);
            t1b = ffma2(w1d[ch], VB.y, t1b);
            t0a = ffma2(w0d[ch], UA.x, t0a);
            t1a = ffma2(w0d[ch], UA.y, t1a);
            t0b = ffma2(w0d[ch], UB.x, t0b);
            t1b = ffma2(w0d[ch], UB.y, t1b);
            t0a = relu2x2(t0a);
            t1a = relu2x2(t1a);
            t0b = relu2x2(t0b);
            t1b = relu2x2(t1b);
            a0A = ffma2(t0a, lwr[ch][0], a0A);
            a1A = ffma2(t1a, lwr[ch][1], a1A);
            a0B = ffma2(t0b, lwr[ch][0], a0B);
            a1B = ffma2(t1b, lwr[ch][1], a1B);
        }
        float2 fA = unpack2(fadd2(a0A, a1A));
        float2 fB = unpack2(fadd2(a0B, a1B));
        float sA = fA.x + fA.y;
        float sB = fB.x + fB.y;
        // 2-level butterfly: lanes 0..7 hold 8 disjoint partials.
#pragma unroll
        for (int off = 16; off >= 8; off >>= 1) {
            sA += __shfl_xor_sync(0xffffffffu, sA, off);
            sB += __shfl_xor_sync(0xffffffffu, sB, off);
        }
        if (lane < 8) {
            atomicAdd(out + 2 * p,     sA);
            atomicAdd(out + 2 * p + 1, sB);
        }

        // ---- Rotate staged indices ----
        rw = rw1; cl = cl1; tp = tp1;
    }
}

extern "C" void kernel_launch(void* const* d_in, const int* in_sizes, int n_in,
                              void* d_out, int out_size) {
    // Identify inputs by unique element counts (immune to metadata ordering).
    const float *h = 0, *g = 0, *conv_w = 0, *conv_b = 0, *lin_w = 0, *lin_b = 0;
    const int *edge_idx = 0, *edge_type = 0;
    for (int i = 0; i < n_in; ++i) {
        switch (in_sizes[i]) {
            case NEDGE * 128: h         = (const float*)d_in[i]; break;
            case 500 * 128:   g         = (const float*)d_in[i]; break;
            case 2 * NEDGE:   edge_idx  = (const int*)d_in[i];   break;
            case NEDGE:       edge_type = (const int*)d_in[i];   break;
            case 96:          conv_w    = (const float*)d_in[i]; break;
            case 32:          conv_b    = (const float*)d_in[i]; break;
            case 4096:        lin_w     = (const float*)d_in[i]; break;
            case 1:           lin_b     = (const float*)d_in[i]; break;
            default: break;
        }
    }
    float* out = (float*)d_out;

    init_kernel<<<(NEDGE + 255) / 256, 256>>>(out, lin_b, edge_idx);
    convkb_kernel<<<G, THREADS>>>(h, g, edge_idx, edge_type,
                                  conv_w, conv_b, lin_w, out);
}

// round 17
// speedup vs baseline: 1.1604x; 1.0270x over previous
#include <cuda_runtime.h>

// ConvKB: score[e] = sum_{c,d} relu(w0c*u_d + w1c*v_d + w2c*r_d + bc) * lw[c,d] + lb
// Warp = (2 ADJACENT edges, 8 channels, all 128 d); block = 32 channels for the pair.
// ZERO global atomics: 5-level interleaved butterflies -> smem partials -> fixed-order
// block sum -> direct STG (+lin_b). Adjacent pairing: 3 vector idx loads, staged 1
// iter ahead. 4 independent FFMA2 chains; relu via (t+|t|), lw pre-scaled 0.5.

#define D 128
#define THREADS 128
#define G 444                 // grid: 148 SMs * 3 blocks
#define NPAIR 25000           // NEDGE/2 exact
#define NEDGE 50000

typedef unsigned long long ull;

__device__ int g_is64;        // 1 if index arrays are int64, 0 if int32

__device__ __forceinline__ ull ffma2(ull a, ull b, ull c) {
    ull d;
    asm("fma.rn.f32x2 %0, %1, %2, %3;" : "=l"(d) : "l"(a), "l"(b), "l"(c));
    return d;
}
__device__ __forceinline__ ull fadd2(ull a, ull b) {
    ull d;
    asm("add.rn.f32x2 %0, %1, %2;" : "=l"(d) : "l"(a), "l"(b));
    return d;
}
// 2*relu(a) packed: a + |a|
__device__ __forceinline__ ull relu2x2(ull a) {
    return fadd2(a, a & 0x7FFFFFFF7FFFFFFFULL);
}
__device__ __forceinline__ ull pack2(float lo, float hi) {
    ull d;
    asm("mov.b64 %0, {%1, %2};" : "=l"(d) : "f"(lo), "f"(hi));
    return d;
}
__device__ __forceinline__ float2 unpack2(ull v) {
    float2 r;
    asm("mov.b64 {%0, %1}, %2;" : "=f"(r.x), "=f"(r.y) : "l"(v));
    return r;
}

// Load the index pair (edge 2p, 2p+1) with one vector load.
__device__ __forceinline__ int2 idx_pair(const int* base, int p, int is64) {
    if (is64) {
        longlong2 t = ((const longlong2*)base)[p];
        return make_int2((int)t.x, (int)t.y);
    } else {
        return ((const int2*)base)[p];
    }
}

// Dtype detection only (out is fully written by the main kernel).
__global__ void detect_kernel(const int* __restrict__ ei) {
    int is64 = 1;
    for (int k = 1; k < 128; k += 2)
        if (ei[k] != 0) { is64 = 0; break; }
    g_is64 = is64;
}

__global__ void __launch_bounds__(THREADS, 3) convkb_kernel(
    const float* __restrict__ h,
    const float* __restrict__ g,
    const int* __restrict__ edge_idx,    // [2,E], int32 or int64
    const int* __restrict__ edge_type,   // [E]
    const float* __restrict__ conv_w,    // [C,3]
    const float* __restrict__ conv_b,    // [C]
    const float* __restrict__ lin_w,     // [C*D]
    const float* __restrict__ lin_b,     // [1]
    float* __restrict__ out)             // [E]
{
    __shared__ float part[8];            // [warp][edgeA/edgeB]

    const int tid  = threadIdx.x;
    const int lane = tid & 31;
    const int warp = tid >> 5;

    // ---- Edge-invariant register state: warp covers channels cb..cb+7 ----
    // Lane L owns d = 4L .. 4L+3 (two packed d-pairs). Shared by both edges.
    const int cb = warp * 8;
    ull w0d[8], w1d[8], w2d[8], bd[8], lwr[8][2];
    {
        const float4* lw4 = (const float4*)lin_w;
#pragma unroll
        for (int ch = 0; ch < 8; ++ch) {
            int c = cb + ch;
            float a0 = conv_w[3 * c + 0], a1 = conv_w[3 * c + 1], a2 = conv_w[3 * c + 2];
            float bb = conv_b[c];
            w0d[ch] = pack2(a0, a0);
            w1d[ch] = pack2(a1, a1);
            w2d[ch] = pack2(a2, a2);
            bd[ch]  = pack2(bb, bb);
            float4 A = lw4[c * 32 + lane];   // lw[c, 4L .. 4L+3]
            lwr[ch][0] = pack2(0.5f * A.x, 0.5f * A.y);   // relu-trick pre-scale
            lwr[ch][1] = pack2(0.5f * A.z, 0.5f * A.w);
        }
    }
    const float lb = lin_b[0];

    const int is64 = g_is64;
    const int* eidx_rows = edge_idx;
    const int* eidx_cols = edge_idx + (is64 ? 2 * NEDGE : NEDGE);

    // ---- Prologue: stage index pairs for pair(0) ----
    int p = (int)blockIdx.x;
    int2 rw = idx_pair(eidx_rows, p, is64);
    int2 cl = idx_pair(eidx_cols, p, is64);
    int2 tp = idx_pair(edge_type, p, is64);

    // All warps in the block follow the same p-sequence -> same trip count; BARs safe.
    for (; p < NPAIR; p += G) {
        // ---- Stage index pairs for next iteration FIRST (longest chain) ----
        int pn = min(p + G, NPAIR - 1);            // clamp: safe, discarded at end
        int2 rw1 = idx_pair(eidx_rows, pn, is64);
        int2 cl1 = idx_pair(eidx_cols, pn, is64);
        int2 tp1 = idx_pair(edge_type, pn, is64);

        // ---- Gathers for current pair ----
        ulonglong2 RA = ((const ulonglong2*)(g + (size_t)tp.x * D))[lane];
        ulonglong2 RB = ((const ulonglong2*)(g + (size_t)tp.y * D))[lane];
        ulonglong2 VA = ((const ulonglong2*)(h + (size_t)cl.x * D))[lane];
        ulonglong2 VB = ((const ulonglong2*)(h + (size_t)cl.y * D))[lane];
        ulonglong2 UA = ((const ulonglong2*)(h + (size_t)rw.x * D))[lane];
        ulonglong2 UB = ((const ulonglong2*)(h + (size_t)rw.y * D))[lane];

        // ---- Compute both edges (4 independent FFMA2 chains; shared params) ----
        ull a0A = 0ULL, a1A = 0ULL, a0B = 0ULL, a1B = 0ULL;
#pragma unroll
        for (int ch = 0; ch < 8; ++ch) {
            ull t0a = ffma2(w2d[ch], RA.x, bd[ch]);
            ull t1a = ffma2(w2d[ch], RA.y, bd[ch]);
            ull t0b = ffma2(w2d[ch], RB.x, bd[ch]);
            ull t1b = ffma2(w2d[ch], RB.y, bd[ch]);
            t0a = ffma2(w1d[ch], VA.x, t0a);
            t1a = ffma2(w1d[ch], VA.y, t1a);
            t0b = ffma2(w1d[ch], VB.x, t0b);
            t1b = ffma2(w1d[ch], VB.y, t1b);
            t0a = ffma2(w0d[ch], UA.x, t0a);
            t1a = ffma2(w0d[ch], UA.y, t1a);
            t0b = ffma2(w0d[ch], UB.x, t0b);
            t1b = ffma2(w0d[ch], UB.y, t1b);
            t0a = relu2x2(t0a);
            t1a = relu2x2(t1a);
            t0b = relu2x2(t0b);
            t1b = relu2x2(t1b);
            a0A = ffma2(t0a, lwr[ch][0], a0A);
            a1A = ffma2(t1a, lwr[ch][1], a1A);
            a0B = ffma2(t0b, lwr[ch][0], a0B);
            a1B = ffma2(t1b, lwr[ch][1], a1B);
        }
        float2 fA = unpack2(fadd2(a0A, a1A));
        float2 fB = unpack2(fadd2(a0B, a1B));
        float sA = fA.x + fA.y;
        float sB = fB.x + fB.y;
        // Full 5-level butterflies, A/B interleaved (chains overlap).
#pragma unroll
        for (int off = 16; off > 0; off >>= 1) {
            sA += __shfl_xor_sync(0xffffffffu, sA, off);
            sB += __shfl_xor_sync(0xffffffffu, sB, off);
        }
        if (lane == 0) {
            part[warp * 2]     = sA;
            part[warp * 2 + 1] = sB;
        }
        __syncthreads();
        if (tid < 2) {
            // Fixed-order sum -> deterministic output, single STG, no atomics.
            float s = ((part[tid] + part[2 + tid]) + (part[4 + tid] + part[6 + tid])) + lb;
            out[2 * p + tid] = s;
        }
        __syncthreads();   // protect part[] before next iteration's writes

        // ---- Rotate staged indices ----
        rw = rw1; cl = cl1; tp = tp1;
    }
}

extern "C" void kernel_launch(void* const* d_in, const int* in_sizes, int n_in,
                              void* d_out, int out_size) {
    // Identify inputs by unique element counts (immune to metadata ordering).
    const float *h = 0, *g = 0, *conv_w = 0, *conv_b = 0, *lin_w = 0, *lin_b = 0;
    const int *edge_idx = 0, *edge_type = 0;
    for (int i = 0; i < n_in; ++i) {
        switch (in_sizes[i]) {
            case NEDGE * 128: h         = (const float*)d_in[i]; break;
            case 500 * 128:   g         = (const float*)d_in[i]; break;
            case 2 * NEDGE:   edge_idx  = (const int*)d_in[i];   break;
            case NEDGE:       edge_type = (const int*)d_in[i];   break;
            case 96:          conv_w    = (const float*)d_in[i]; break;
            case 32:          conv_b    = (const float*)d_in[i]; break;
            case 4096:        lin_w     = (const float*)d_in[i]; break;
            case 1:           lin_b     = (const float*)d_in[i]; break;
            default: break;
        }
    }
    float* out = (float*)d_out;

    detect_kernel<<<1, 1>>>(edge_idx);
    convkb_kernel<<<G, THREADS>>>(h, g, edge_idx, edge_type,
                                  conv_w, conv_b, lin_w, lin_b, out);
}